// round 11
// baseline (speedup 1.0000x reference)
#include <cuda_runtime.h>
#include <cstdint>

#define NPTS  4096
#define BATCH 8
#define KNN_K 16

// scratch: neighbor indices (original within-batch indices), 2MB
__device__ int g_idx[BATCH * NPTS * KNN_K];
// scratch: pooled features, 96 floats per point packed as 48 u64, 12.6MB
__device__ __align__(16) unsigned long long g_feat[BATCH * NPTS * 48];

// ---------------------------------------------------------------------------
// packed f32x2 helpers
// ---------------------------------------------------------------------------
__device__ __forceinline__ unsigned long long ffma2(unsigned long long a,
                                                    unsigned long long b,
                                                    unsigned long long c) {
    unsigned long long d;
    asm("fma.rn.f32x2 %0, %1, %2, %3;" : "=l"(d) : "l"(a), "l"(b), "l"(c));
    return d;
}
__device__ __forceinline__ unsigned long long add2(unsigned long long a,
                                                   unsigned long long b) {
    unsigned long long d;
    asm("add.rn.f32x2 %0, %1, %2;" : "=l"(d) : "l"(a), "l"(b));
    return d;
}
__device__ __forceinline__ unsigned long long mul2(unsigned long long a,
                                                   unsigned long long b) {
    unsigned long long d;
    asm("mul.rn.f32x2 %0, %1, %2;" : "=l"(d) : "l"(a), "l"(b));
    return d;
}
__device__ __forceinline__ unsigned long long pack2(float lo, float hi) {
    unsigned long long p;
    asm("mov.b64 %0, {%1, %2};" : "=l"(p) : "f"(lo), "f"(hi));
    return p;
}
__device__ __forceinline__ void unpack2(unsigned long long p, float& lo, float& hi) {
    asm("mov.b64 {%0, %1}, %2;" : "=f"(lo), "=f"(hi) : "l"(p));
}

// sorted u64 lower-half bitonic merge: a (sorted asc) x b (sorted asc) -> a
__device__ __forceinline__ void merge16(unsigned long long* a,
                                        const unsigned long long* bsrc) {
    unsigned long long L[KNN_K];
#pragma unroll
    for (int i = 0; i < KNN_K; ++i) {
        unsigned long long bb = bsrc[KNN_K - 1 - i];
        L[i] = (a[i] < bb) ? a[i] : bb;
    }
#pragma unroll
    for (int j = 8; j >= 1; j >>= 1) {
#pragma unroll
        for (int i = 0; i < KNN_K; ++i) {
            if ((i & j) == 0) {
                unsigned long long lo = L[i], hi = L[i | j];
                unsigned long long mn = (lo < hi) ? lo : hi;
                unsigned long long mx = (lo < hi) ? hi : lo;
                L[i] = mn; L[i | j] = mx;
            }
        }
    }
#pragma unroll
    for (int i = 0; i < KNN_K; ++i) a[i] = L[i];
}

// ---------------------------------------------------------------------------
// Kernel 1: exact KNN, 4 threads/query (quarter ranges), buffered top-16.
// Hot loop: groups of 4 candidates (two packed pairs), filter distance
// dx^2+dy^2, 4->1 min reduction, ONE branch per group; individual checks +
// FIFO pushes only inside the (increasingly rare) taken branch. Drains
// recompute the EXACT reference-formula distance and re-check with the
// bit-exact u-compare before the validated cascade -> selection identical.
// ---------------------------------------------------------------------------
#define QCAP 12   // per-lane FIFO capacity (u32 entries); drain at cnt>=4

extern "C" __global__ void __launch_bounds__(256)
knn_kernel(const float* __restrict__ x) {
    extern __shared__ __align__(16) char smem_raw[];
    float* xs = (float*)smem_raw;                                      // 16KB
    float* ys = xs + NPTS;                                             // 16KB
    unsigned long long* mbuf = (unsigned long long*)(ys + NPTS);       // 26.1KB
    unsigned* qbuf = (unsigned*)(mbuf + 3 * 64 * 17);                  // 12KB

    const int tid = threadIdx.x;
    const int b   = blockIdx.y;
    const float2* __restrict__ xb = ((const float2*)x) + (size_t)b * NPTS;

    for (int i = tid; i < NPTS; i += 256) {
        float2 v = xb[i];
        xs[i] = v.x;
        ys[i] = v.y;
    }
    __syncthreads();

    const int qloc = tid & 63;
    const int part = tid >> 6;                    // warp-uniform (2 warps/part)
    const int q    = blockIdx.x * 64 + qloc;
    const float qx = xs[q], qy = ys[q];
    // exact reference sq for the drain formula
    const float qsq = __fadd_rn(__fmul_rn(qx, qx), __fmul_rn(qy, qy));

    // sentinel = mapped(+INF); unmaps to float +INF for the threshold
    unsigned bu[KNN_K];
    int      bi[KNN_K];
#pragma unroll
    for (int s = 0; s < KNN_K; ++s) { bu[s] = 0xFF800000u; bi[s] = 0; }

    const int jbeg = part * (NPTS / 4);
    int cnt = 0;
    const float MARGIN = 1e-4f;                   // >> |filter - reference| slop
    float worstf = __int_as_float(0x7F800000);    // +INF

    auto insert = [&](unsigned u, int j) {
        bool c[KNN_K];
#pragma unroll
        for (int s = 0; s < KNN_K; ++s) c[s] = (u < bu[s]);
#pragma unroll
        for (int s = KNN_K - 1; s >= 1; --s) {
            bu[s] = c[s - 1] ? bu[s - 1] : (c[s] ? u : bu[s]);
            bi[s] = c[s - 1] ? bi[s - 1] : (c[s] ? j : bi[s]);
        }
        if (c[0]) { bu[0] = u; bi[0] = j; }
    };

    auto drain = [&]() {
#pragma unroll 1
        for (int t = 0; t < cnt; ++t) {           // divergent per-lane count
            int j = (int)qbuf[t * 256 + tid];
            float px = xs[j], py = ys[j];
            // exact reference formula, no FMA contraction
            float ps  = __fadd_rn(__fmul_rn(px, px), __fmul_rn(py, py));
            float dot = __fadd_rn(__fmul_rn(qx, px), __fmul_rn(qy, py));
            float d   = __fsub_rn(__fadd_rn(qsq, ps), __fmul_rn(2.0f, dot));
            int ib = __float_as_int(d);
            unsigned u = (ib >= 0) ? ((unsigned)ib ^ 0x80000000u) : ~(unsigned)ib;
            if (u < bu[KNN_K - 1]) insert(u, j);
        }
        cnt = 0;
        // unmap bu[15] -> float threshold + margin (sentinel -> +INF)
        unsigned u15 = bu[KNN_K - 1];
        int ib = (u15 & 0x80000000u) ? (int)(u15 ^ 0x80000000u) : (int)~u15;
        worstf = __int_as_float(ib) + MARGIN;
    };

    const unsigned long long nqx2 = pack2(-qx, -qx);
    const unsigned long long nqy2 = pack2(-qy, -qy);

#pragma unroll 1
    for (int blk = 0; blk < NPTS / 4; blk += 8) {
#pragma unroll
        for (int g = 0; g < 2; ++g) {
            const int j = jbeg + blk + g * 4;
            ulonglong2 px = *(const ulonglong2*)(xs + j);   // 4 x-coords
            ulonglong2 py = *(const ulonglong2*)(ys + j);   // 4 y-coords
            unsigned long long dxa = add2(px.x, nqx2);
            unsigned long long dxb = add2(px.y, nqx2);
            unsigned long long dya = add2(py.x, nqy2);
            unsigned long long dyb = add2(py.y, nqy2);
            unsigned long long dva = ffma2(dxa, dxa, mul2(dya, dya));
            unsigned long long dvb = ffma2(dxb, dxb, mul2(dyb, dyb));
            float d0, d1, d2, d3;
            unpack2(dva, d0, d1);
            unpack2(dvb, d2, d3);
            float mn = fminf(fminf(d0, d1), fminf(d2, d3));
            if (mn < worstf) {                    // one branch per 4 candidates
                if (d0 < worstf) { qbuf[cnt * 256 + tid] = (unsigned)j;       ++cnt; }
                if (d1 < worstf) { qbuf[cnt * 256 + tid] = (unsigned)(j + 1); ++cnt; }
                if (d2 < worstf) { qbuf[cnt * 256 + tid] = (unsigned)(j + 2); ++cnt; }
                if (d3 < worstf) { qbuf[cnt * 256 + tid] = (unsigned)(j + 3); ++cnt; }
            }
        }
        if (__any_sync(0xFFFFFFFFu, cnt >= QCAP - 8)) drain();
    }
    drain();                                      // leftovers

    // parts 1..3 publish their sorted lists
    if (part != 0) {
        unsigned long long* dst = mbuf + ((part - 1) * 64 + qloc) * 17;
#pragma unroll
        for (int s = 0; s < KNN_K; ++s)
            dst[s] = ((unsigned long long)bu[s] << 32) | (unsigned)bi[s];
    }
    __syncthreads();

    if (part == 0) {
        unsigned long long L[KNN_K];
#pragma unroll
        for (int s = 0; s < KNN_K; ++s)
            L[s] = ((unsigned long long)bu[s] << 32) | (unsigned)bi[s];

        merge16(L, mbuf + (0 * 64 + qloc) * 17);
        unsigned long long M[KNN_K];
        const unsigned long long* p2 = mbuf + (1 * 64 + qloc) * 17;
#pragma unroll
        for (int s = 0; s < KNN_K; ++s) M[s] = p2[s];
        merge16(M, mbuf + (2 * 64 + qloc) * 17);
        merge16(L, M);

        int* outp = g_idx + ((size_t)b * NPTS + q) * KNN_K;
#pragma unroll
        for (int s = 0; s < KNN_K; ++s)
            outp[s] = (int)(L[s] & 0xFFFFFFFFu);
    }
}

// ---------------------------------------------------------------------------
// Kernel 2a: pooling (layers 1-4), NEIGHBOR-split: 2 threads/point, each
// handles 8 of the 16 neighbors across ALL 96 features (balanced), then the
// 48 packed accumulators are combined pairwise via shfl_xor(1). Only the
// k-summation order changes vs the reference (k 0-7 + k 8-15) -> ~1e-7 noise.
// ---------------------------------------------------------------------------
struct __align__(16) SmemPool {
    float2 pts[NPTS];          // 32KB
    float w1[32];              // [8][4]
    float w2[64];              // [8][8]
    float w3[128];             // [16][8]
    float w4[1024];            // [64][16]
    float mw[64];              // [4][16]
    float mb[4];
    float s1[8],  b1[8];
    float s2[8],  b2[8];
    float s3[16], b3[16];
    float s4[64], b4[64];
    unsigned long long bias[2][24];  // per-khalf packed mlp-bias table
};

extern "C" __global__ void __launch_bounds__(128)
pool_kernel(const float* __restrict__ x,
            const float* __restrict__ w1, const float* __restrict__ w2,
            const float* __restrict__ w3, const float* __restrict__ w4,
            const float* __restrict__ mw, const float* __restrict__ mb,
            const float* __restrict__ bn1, const float* __restrict__ bn2,
            const float* __restrict__ bn3, const float* __restrict__ bn4) {
    extern __shared__ __align__(16) char smem_raw[];
    SmemPool* sm = (SmemPool*)smem_raw;

    const int tid = threadIdx.x;
    const int b   = blockIdx.y;

    for (int i = tid; i < NPTS; i += 128) sm->pts[i] = ((const float2*)x)[(size_t)b * NPTS + i];
    for (int i = tid; i < 32;   i += 128) sm->w1[i] = w1[i];
    for (int i = tid; i < 64;   i += 128) sm->w2[i] = w2[i];
    for (int i = tid; i < 128;  i += 128) sm->w3[i] = w3[i];
    for (int i = tid; i < 1024; i += 128) sm->w4[i] = w4[i];
    for (int i = tid; i < 64;   i += 128) sm->mw[i] = mw[i];
    if (tid < 4) sm->mb[tid] = mb[tid];
    for (int i = tid; i < 8;  i += 128) {
        float s = bn1[i] * rsqrtf(bn1[24 + i] + 1e-5f);
        sm->s1[i] = s; sm->b1[i] = bn1[8 + i] - bn1[16 + i] * s;
        float t = bn2[i] * rsqrtf(bn2[24 + i] + 1e-5f);
        sm->s2[i] = t; sm->b2[i] = bn2[8 + i] - bn2[16 + i] * t;
    }
    for (int i = tid; i < 16; i += 128) {
        float s = bn3[i] * rsqrtf(bn3[48 + i] + 1e-5f);
        sm->s3[i] = s; sm->b3[i] = bn3[16 + i] - bn3[32 + i] * s;
    }
    for (int i = tid; i < 64; i += 128) {
        float s = bn4[i] * rsqrtf(bn4[192 + i] + 1e-5f);
        sm->s4[i] = s; sm->b4[i] = bn4[64 + i] - bn4[128 + i] * s;
    }
    __syncthreads();

    // build per-khalf packed bias table (needs sm->mb loaded)
    if (tid < 48) {
        int h = tid / 24, i = tid % 24;
        float c;
        if (h == 0) c = (i < 4) ? sm->mb[0] : (i < 8) ? sm->mb[1]
                       : (i < 16) ? sm->mb[2] : sm->mb[3];
        else        c = sm->mb[3];
        sm->bias[h][i] = pack2(c, c);
    }
    __syncthreads();

    const int nloc  = tid >> 1;
    const int khalf = tid & 1;                    // which 8 neighbors
    const int n     = blockIdx.x * 64 + nloc;
    const int gq    = b * NPTS + n;
    const int* __restrict__ gi = g_idx + (size_t)gq * KNN_K + khalf * 8;

    unsigned long long facc[48];
#pragma unroll
    for (int i = 0; i < 48; ++i) facc[i] = 0ULL;

    const float2 ctr = sm->pts[n];

#pragma unroll 1
    for (int k = 0; k < 8; ++k) {
        const int kk  = khalf * 8 + k;
        const int nbk = gi[k];
        const float2 P = sm->pts[nbk];
        const unsigned long long m1p = pack2(sm->mw[kk],      sm->mw[kk]);
        const unsigned long long m2p = pack2(sm->mw[16 + kk], sm->mw[16 + kk]);
        const unsigned long long m3p = pack2(sm->mw[32 + kk], sm->mw[32 + kk]);
        const unsigned long long m4p = pack2(sm->mw[48 + kk], sm->mw[48 + kk]);

        // layer 1: 4 -> 8
        float h1[8];
#pragma unroll
        for (int o = 0; o < 8; o += 2) {
#pragma unroll
            for (int t = 0; t < 2; ++t) {
                float4 w = *(const float4*)(sm->w1 + (o + t) * 4);
                float v = P.x * w.x + P.y * w.y + ctr.x * w.z + ctr.y * w.w;
                h1[o + t] = fmaxf(fmaf(v, sm->s1[o + t], sm->b1[o + t]), 0.0f);
            }
            facc[o / 2] = ffma2(pack2(h1[o], h1[o + 1]), m1p, facc[o / 2]);
        }
        // layer 2: 8 -> 8
        float h2[8];
#pragma unroll
        for (int o = 0; o < 8; o += 2) {
#pragma unroll
            for (int t = 0; t < 2; ++t) {
                const float4* w = (const float4*)(sm->w2 + (o + t) * 8);
                float4 wa = w[0], wb = w[1];
                float v = h1[0] * wa.x + h1[1] * wa.y + h1[2] * wa.z + h1[3] * wa.w
                        + h1[4] * wb.x + h1[5] * wb.y + h1[6] * wb.z + h1[7] * wb.w;
                h2[o + t] = fmaxf(fmaf(v, sm->s2[o + t], sm->b2[o + t]), 0.0f);
            }
            facc[4 + o / 2] = ffma2(pack2(h2[o], h2[o + 1]), m2p, facc[4 + o / 2]);
        }
        // layer 3: 8 -> 16 (packed pairs for layer-4 dots)
        unsigned long long h3p[8];
#pragma unroll
        for (int o = 0; o < 16; o += 2) {
            float vv[2];
#pragma unroll
            for (int t = 0; t < 2; ++t) {
                const float4* w = (const float4*)(sm->w3 + (o + t) * 8);
                float4 wa = w[0], wb = w[1];
                float v = h2[0] * wa.x + h2[1] * wa.y + h2[2] * wa.z + h2[3] * wa.w
                        + h2[4] * wb.x + h2[5] * wb.y + h2[6] * wb.z + h2[7] * wb.w;
                vv[t] = fmaxf(fmaf(v, sm->s3[o + t], sm->b3[o + t]), 0.0f);
            }
            h3p[o / 2] = pack2(vv[0], vv[1]);
            facc[8 + o / 2] = ffma2(h3p[o / 2], m3p, facc[8 + o / 2]);
        }
        // layer 4: all 64 outputs
#pragma unroll 1
        for (int o = 0; o < 64; o += 2) {
            float vv[2];
#pragma unroll
            for (int t = 0; t < 2; ++t) {
                const ulonglong2* wrow = (const ulonglong2*)(sm->w4 + (o + t) * 16);
                ulonglong2 wa = wrow[0], wb = wrow[1], wc = wrow[2], wd = wrow[3];
                unsigned long long acc = ffma2(h3p[0], wa.x, 0ULL);
                acc = ffma2(h3p[1], wa.y, acc);
                acc = ffma2(h3p[2], wb.x, acc);
                acc = ffma2(h3p[3], wb.y, acc);
                acc = ffma2(h3p[4], wc.x, acc);
                acc = ffma2(h3p[5], wc.y, acc);
                acc = ffma2(h3p[6], wd.x, acc);
                acc = ffma2(h3p[7], wd.y, acc);
                float lo, hi; unpack2(acc, lo, hi);
                float v = lo + hi;
                vv[t] = fmaxf(fmaf(v, sm->s4[o + t], sm->b4[o + t]), 0.0f);
            }
            facc[16 + o / 2] = ffma2(pack2(vv[0], vv[1]), m4p, facc[16 + o / 2]);
        }
    }

    // pairwise combine across the two k-halves (lanes 2i / 2i+1) + bias.
    // khalf 0 keeps features [0..48) (facc[0..24)); khalf 1 keeps [48..96).
    const unsigned long long* bt = sm->bias[khalf];
#pragma unroll
    for (int i = 0; i < 24; ++i) {
        unsigned long long rlo = __shfl_xor_sync(0xFFFFFFFFu, facc[i],      1);
        unsigned long long rhi = __shfl_xor_sync(0xFFFFFFFFu, facc[24 + i], 1);
        unsigned long long s = khalf ? add2(facc[24 + i], rhi)
                                     : add2(facc[i],      rlo);
        facc[i] = add2(s, bt[i]);
    }

    ulonglong2* dst = (ulonglong2*)(g_feat + (size_t)gq * 48 + khalf * 24);
#pragma unroll
    for (int i = 0; i < 12; ++i)
        dst[i] = make_ulonglong2(facc[2 * i], facc[2 * i + 1]);
}

// ---------------------------------------------------------------------------
// Kernel 2b: final 96x96 GEMM + BN/ReLU + L2 normalize
// (byte-identical to rounds 6-10)
// ---------------------------------------------------------------------------
struct __align__(16) SmemGemm {
    float w5[9216];            // [96][96]
    float s5[96], b5[96];
};

extern "C" __global__ void __launch_bounds__(128)
gemm_kernel(const float* __restrict__ w5, const float* __restrict__ bn5,
            float* __restrict__ out) {
    extern __shared__ __align__(16) char smem_raw[];
    SmemGemm* sm = (SmemGemm*)smem_raw;

    const int tid = threadIdx.x;
    const int b   = blockIdx.y;

    for (int i = tid; i < 9216; i += 128) sm->w5[i] = w5[i];
    for (int i = tid; i < 96; i += 128) {
        float s = bn5[i] * rsqrtf(bn5[288 + i] + 1e-5f);
        sm->s5[i] = s; sm->b5[i] = bn5[96 + i] - bn5[192 + i] * s;
    }
    __syncthreads();

    const int half = tid & 1;
    const int n    = blockIdx.x * 64 + (tid >> 1);
    const int gq   = b * NPTS + n;

    unsigned long long fh[24];
    const ulonglong2* fsrc = (const ulonglong2*)(g_feat + (size_t)gq * 48 + half * 24);
#pragma unroll
    for (int i = 0; i < 12; ++i) {
        ulonglong2 t = fsrc[i];
        fh[2 * i] = t.x; fh[2 * i + 1] = t.y;
    }

    const int obase = half * 48;
    float* __restrict__ mybase = out + (size_t)gq * 96 + obase;
    float ss = 0.0f;

#pragma unroll 1
    for (int o = 0; o < 96; ++o) {
        const ulonglong2* wrow = (const ulonglong2*)(sm->w5 + o * 96 + half * 48);
        unsigned long long a0 = 0ULL, a1 = 0ULL;
#pragma unroll
        for (int j = 0; j < 12; ++j) {
            ulonglong2 w = wrow[j];
            a0 = ffma2(fh[2 * j],     w.x, a0);
            a1 = ffma2(fh[2 * j + 1], w.y, a1);
        }
        float lo, hi; unpack2(add2(a0, a1), lo, hi);
        float ph = lo + hi;
        float full = ph + __shfl_xor_sync(0xFFFFFFFFu, ph, 1);
        float v = fmaxf(fmaf(full, sm->s5[o], sm->b5[o]), 0.0f);
        ss = fmaf(v, v, ss);
        const int rel = o - obase;
        if ((unsigned)rel < 48u) mybase[rel] = v;   // unnormalized, own half
    }

    const float rn = rsqrtf(ss);
    float4* o4 = (float4*)mybase;
#pragma unroll 3
    for (int i = 0; i < 12; ++i) {
        float4 v = o4[i];
        v.x *= rn; v.y *= rn; v.z *= rn; v.w *= rn;
        o4[i] = v;
    }
}

// ---------------------------------------------------------------------------
// launch
// ---------------------------------------------------------------------------
extern "C" void kernel_launch(void* const* d_in, const int* in_sizes, int n_in,
                              void* d_out, int out_size) {
    const float* x   = (const float*)d_in[0];
    const float* w1  = (const float*)d_in[1];
    const float* w2  = (const float*)d_in[2];
    const float* w3  = (const float*)d_in[3];
    const float* w4  = (const float*)d_in[4];
    const float* w5  = (const float*)d_in[5];
    const float* mw  = (const float*)d_in[6];
    const float* mb  = (const float*)d_in[7];
    const float* bn1 = (const float*)d_in[8];
    const float* bn2 = (const float*)d_in[9];
    const float* bn3 = (const float*)d_in[10];
    const float* bn4 = (const float*)d_in[11];
    const float* bn5 = (const float*)d_in[12];

    const size_t knn_smem  = NPTS * 8 + 3 * 64 * 17 * 8 + 256 * QCAP * 4; // ~70KB
    const size_t pool_smem = sizeof(SmemPool);            // ~39.2KB
    const size_t gemm_smem = sizeof(SmemGemm);            // ~37.6KB

    cudaFuncSetAttribute(knn_kernel,  cudaFuncAttributeMaxDynamicSharedMemorySize, (int)knn_smem);
    cudaFuncSetAttribute(pool_kernel, cudaFuncAttributeMaxDynamicSharedMemorySize, (int)pool_smem);
    cudaFuncSetAttribute(gemm_kernel, cudaFuncAttributeMaxDynamicSharedMemorySize, (int)gemm_smem);

    dim3 grid(NPTS / 64, BATCH);   // 64 x 8 = 512 blocks
    knn_kernel<<<grid, 256, knn_smem>>>(x);
    pool_kernel<<<grid, 128, pool_smem>>>(x, w1, w2, w3, w4, mw, mb,
                                          bn1, bn2, bn3, bn4);
    gemm_kernel<<<grid, 128, gemm_smem>>>(w5, bn5, (float*)d_out);
}

// round 12
// speedup vs baseline: 1.2977x; 1.2977x over previous
#include <cuda_runtime.h>
#include <cstdint>

#define NPTS  4096
#define BATCH 8
#define KNN_K 16

// scratch: neighbor indices (original within-batch indices), 2MB
__device__ int g_idx[BATCH * NPTS * KNN_K];
// scratch: pooled features, 96 floats per point packed as 48 u64, 12.6MB
__device__ __align__(16) unsigned long long g_feat[BATCH * NPTS * 48];

// ---------------------------------------------------------------------------
// packed f32x2 helpers
// ---------------------------------------------------------------------------
__device__ __forceinline__ unsigned long long ffma2(unsigned long long a,
                                                    unsigned long long b,
                                                    unsigned long long c) {
    unsigned long long d;
    asm("fma.rn.f32x2 %0, %1, %2, %3;" : "=l"(d) : "l"(a), "l"(b), "l"(c));
    return d;
}
__device__ __forceinline__ unsigned long long add2(unsigned long long a,
                                                   unsigned long long b) {
    unsigned long long d;
    asm("add.rn.f32x2 %0, %1, %2;" : "=l"(d) : "l"(a), "l"(b));
    return d;
}
__device__ __forceinline__ unsigned long long mul2(unsigned long long a,
                                                   unsigned long long b) {
    unsigned long long d;
    asm("mul.rn.f32x2 %0, %1, %2;" : "=l"(d) : "l"(a), "l"(b));
    return d;
}
__device__ __forceinline__ unsigned long long pack2(float lo, float hi) {
    unsigned long long p;
    asm("mov.b64 %0, {%1, %2};" : "=l"(p) : "f"(lo), "f"(hi));
    return p;
}
__device__ __forceinline__ void unpack2(unsigned long long p, float& lo, float& hi) {
    asm("mov.b64 {%0, %1}, %2;" : "=f"(lo), "=f"(hi) : "l"(p));
}

// sorted u64 lower-half bitonic merge: a (sorted asc) x b (sorted asc) -> a
__device__ __forceinline__ void merge16(unsigned long long* a,
                                        const unsigned long long* bsrc) {
    unsigned long long L[KNN_K];
#pragma unroll
    for (int i = 0; i < KNN_K; ++i) {
        unsigned long long bb = bsrc[KNN_K - 1 - i];
        L[i] = (a[i] < bb) ? a[i] : bb;
    }
#pragma unroll
    for (int j = 8; j >= 1; j >>= 1) {
#pragma unroll
        for (int i = 0; i < KNN_K; ++i) {
            if ((i & j) == 0) {
                unsigned long long lo = L[i], hi = L[i | j];
                unsigned long long mn = (lo < hi) ? lo : hi;
                unsigned long long mx = (lo < hi) ? hi : lo;
                L[i] = mn; L[i | j] = mx;
            }
        }
    }
#pragma unroll
    for (int i = 0; i < KNN_K; ++i) a[i] = L[i];
}

// ---------------------------------------------------------------------------
// Kernel 1: exact KNN, 4 threads/query (quarter ranges), buffered top-16.
// (byte-identical to the validated round-9 version: packed f32x2 distance,
//  bit-exact per-half RN vs the scalar reference formula; u32 FIFO pushes;
//  drains recompute the exact scalar distance + u-compare + cascade;
//  4-way sorted-list bitonic merge)
// ---------------------------------------------------------------------------
#define QCAP 16   // per-lane FIFO capacity (u32 entries)

extern "C" __global__ void __launch_bounds__(256)
knn_kernel(const float* __restrict__ x) {
    extern __shared__ __align__(16) char smem_raw[];
    float2* sxy = (float2*)smem_raw;                                   // 32KB
    float*  ssq = (float*)(smem_raw + NPTS * 8);                       // 16KB
    unsigned long long* mbuf =
        (unsigned long long*)(smem_raw + NPTS * 12);                   // 3*64*17*8
    unsigned* qbuf = (unsigned*)(mbuf + 3 * 64 * 17);                  // 16KB

    const int tid = threadIdx.x;
    const int b   = blockIdx.y;
    const float2* __restrict__ xb = ((const float2*)x) + (size_t)b * NPTS;

    for (int i = tid; i < NPTS; i += 256) {
        float2 v = xb[i];
        sxy[i] = v;
        ssq[i] = __fadd_rn(__fmul_rn(v.x, v.x), __fmul_rn(v.y, v.y));
    }
    __syncthreads();

    const int qloc = tid & 63;
    const int part = tid >> 6;                    // warp-uniform (2 warps/part)
    const int q    = blockIdx.x * 64 + qloc;
    const float2 qv = sxy[q];
    const float qx = qv.x, qy = qv.y, qsq = ssq[q];

    // sentinel = mapped(+INF); unmaps to float +INF for the threshold
    unsigned bu[KNN_K];
    int      bi[KNN_K];
#pragma unroll
    for (int s = 0; s < KNN_K; ++s) { bu[s] = 0xFF800000u; bi[s] = 0; }

    const int jbeg = part * (NPTS / 4);
    int cnt = 0;
    float worstf = __int_as_float(0x7F800000);    // +INF

    auto insert = [&](unsigned u, int j) {
        bool c[KNN_K];
#pragma unroll
        for (int s = 0; s < KNN_K; ++s) c[s] = (u < bu[s]);
#pragma unroll
        for (int s = KNN_K - 1; s >= 1; --s) {
            bu[s] = c[s - 1] ? bu[s - 1] : (c[s] ? u : bu[s]);
            bi[s] = c[s - 1] ? bi[s - 1] : (c[s] ? j : bi[s]);
        }
        if (c[0]) { bu[0] = u; bi[0] = j; }
    };

    auto drain = [&]() {
#pragma unroll 1
        for (int t = 0; t < cnt; ++t) {           // divergent per-lane count
            int j = (int)qbuf[t * 256 + tid];
            float2 p = sxy[j];
            float ps = ssq[j];
            // exact reference formula, no FMA contraction
            float dot = __fadd_rn(__fmul_rn(qx, p.x), __fmul_rn(qy, p.y));
            float d   = __fsub_rn(__fadd_rn(qsq, ps), __fmul_rn(2.0f, dot));
            int ib = __float_as_int(d);
            unsigned u = (ib >= 0) ? ((unsigned)ib ^ 0x80000000u) : ~(unsigned)ib;
            if (u < bu[KNN_K - 1]) insert(u, j);
        }
        cnt = 0;
        // unmap bu[15] -> float threshold (sentinel -> +INF)
        unsigned u15 = bu[KNN_K - 1];
        int ib = (u15 & 0x80000000u) ? (int)(u15 ^ 0x80000000u) : (int)~u15;
        worstf = __int_as_float(ib);
    };

    const unsigned long long qx2 = pack2(qx, qx);
    const unsigned long long qy2 = pack2(qy, qy);
    const unsigned long long qs2 = pack2(qsq, qsq);
    const unsigned long long n22 = pack2(-2.0f, -2.0f);

#pragma unroll 1
    for (int blk = 0; blk < NPTS / 4; blk += 8) {
#pragma unroll
        for (int pp = 0; pp < 4; ++pp) {
            const int j = jbeg + blk + pp * 2;
            float4 pxy = *(const float4*)(sxy + j);        // x0,y0,x1,y1
            float2 ps  = *(const float2*)(ssq + j);
            unsigned long long px  = pack2(pxy.x, pxy.z);
            unsigned long long py  = pack2(pxy.y, pxy.w);
            unsigned long long psq = pack2(ps.x, ps.y);
            // per-half identical rounding to the scalar reference:
            unsigned long long dot = add2(mul2(qx2, px), mul2(qy2, py));
            unsigned long long dv  = add2(add2(qs2, psq), mul2(n22, dot));
            float d0, d1; unpack2(dv, d0, d1);
            if (d0 < worstf) { qbuf[cnt * 256 + tid] = (unsigned)j;       ++cnt; }
            if (d1 < worstf) { qbuf[cnt * 256 + tid] = (unsigned)(j + 1); ++cnt; }
        }
        if (__any_sync(0xFFFFFFFFu, cnt >= QCAP - 8)) drain();
    }
    drain();                                      // leftovers

    // parts 1..3 publish their sorted lists
    if (part != 0) {
        unsigned long long* dst = mbuf + ((part - 1) * 64 + qloc) * 17;
#pragma unroll
        for (int s = 0; s < KNN_K; ++s)
            dst[s] = ((unsigned long long)bu[s] << 32) | (unsigned)bi[s];
    }
    __syncthreads();

    if (part == 0) {
        unsigned long long L[KNN_K];
#pragma unroll
        for (int s = 0; s < KNN_K; ++s)
            L[s] = ((unsigned long long)bu[s] << 32) | (unsigned)bi[s];

        merge16(L, mbuf + (0 * 64 + qloc) * 17);
        unsigned long long M[KNN_K];
        const unsigned long long* p2 = mbuf + (1 * 64 + qloc) * 17;
#pragma unroll
        for (int s = 0; s < KNN_K; ++s) M[s] = p2[s];
        merge16(M, mbuf + (2 * 64 + qloc) * 17);
        merge16(L, M);

        int* outp = g_idx + ((size_t)b * NPTS + q) * KNN_K;
#pragma unroll
        for (int s = 0; s < KNN_K; ++s)
            outp[s] = (int)(L[s] & 0xFFFFFFFFu);
    }
}

// ---------------------------------------------------------------------------
// Kernel 2a: pooling (layers 1-4 over 16 neighbors), REBALANCED feature-split:
// part 0 -> features [0..64)  (layer1/2/3 pools + layer4 outputs 0..31)
// part 1 -> features [64..96) (layer4 outputs 32..63)
// Per-neighbor cost: part0 ~628 vs part1 ~612 (was 492 vs 748).
// Accumulation order per feature unchanged -> bit-identical g_feat.
// ---------------------------------------------------------------------------
struct __align__(16) SmemPool {
    float2 pts[NPTS];          // 32KB
    float w1[32];              // [8][4]
    float w2[64];              // [8][8]
    float w3[128];             // [16][8]
    float w4[1024];            // [64][16]
    float mw[64];              // [4][16]
    float mb[4];
    float s1[8],  b1[8];
    float s2[8],  b2[8];
    float s3[16], b3[16];
    float s4[64], b4[64];
};

extern "C" __global__ void __launch_bounds__(128)
pool_kernel(const float* __restrict__ x,
            const float* __restrict__ w1, const float* __restrict__ w2,
            const float* __restrict__ w3, const float* __restrict__ w4,
            const float* __restrict__ mw, const float* __restrict__ mb,
            const float* __restrict__ bn1, const float* __restrict__ bn2,
            const float* __restrict__ bn3, const float* __restrict__ bn4) {
    extern __shared__ __align__(16) char smem_raw[];
    SmemPool* sm = (SmemPool*)smem_raw;

    const int tid = threadIdx.x;
    const int b   = blockIdx.y;

    for (int i = tid; i < NPTS; i += 128) sm->pts[i] = ((const float2*)x)[(size_t)b * NPTS + i];
    for (int i = tid; i < 32;   i += 128) sm->w1[i] = w1[i];
    for (int i = tid; i < 64;   i += 128) sm->w2[i] = w2[i];
    for (int i = tid; i < 128;  i += 128) sm->w3[i] = w3[i];
    for (int i = tid; i < 1024; i += 128) sm->w4[i] = w4[i];
    for (int i = tid; i < 64;   i += 128) sm->mw[i] = mw[i];
    if (tid < 4) sm->mb[tid] = mb[tid];
    for (int i = tid; i < 8;  i += 128) {
        float s = bn1[i] * rsqrtf(bn1[24 + i] + 1e-5f);
        sm->s1[i] = s; sm->b1[i] = bn1[8 + i] - bn1[16 + i] * s;
        float t = bn2[i] * rsqrtf(bn2[24 + i] + 1e-5f);
        sm->s2[i] = t; sm->b2[i] = bn2[8 + i] - bn2[16 + i] * t;
    }
    for (int i = tid; i < 16; i += 128) {
        float s = bn3[i] * rsqrtf(bn3[48 + i] + 1e-5f);
        sm->s3[i] = s; sm->b3[i] = bn3[16 + i] - bn3[32 + i] * s;
    }
    for (int i = tid; i < 64; i += 128) {
        float s = bn4[i] * rsqrtf(bn4[192 + i] + 1e-5f);
        sm->s4[i] = s; sm->b4[i] = bn4[64 + i] - bn4[128 + i] * s;
    }
    __syncthreads();

    const int nloc = tid & 63;
    const int part = tid >> 6;                    // warp-uniform
    const int n    = blockIdx.x * 64 + nloc;
    const int gq   = b * NPTS + n;
    const int* __restrict__ gi = g_idx + (size_t)gq * KNN_K;

    // part0: facc[0..32) = features [0..64); part1: facc[0..16) = features [64..96)
    unsigned long long facc[32];
#pragma unroll
    for (int i = 0; i < 32; ++i) facc[i] = 0ULL;

    const float2 ctr = sm->pts[n];
    const int obeg = part ? 32 : 0;
    const int oend = part ? 64 : 32;

#pragma unroll 1
    for (int k = 0; k < KNN_K; ++k) {
        const int nbk = gi[k];
        const float2 P = sm->pts[nbk];
        const unsigned long long m1p = pack2(sm->mw[k],      sm->mw[k]);
        const unsigned long long m2p = pack2(sm->mw[16 + k], sm->mw[16 + k]);
        const unsigned long long m3p = pack2(sm->mw[32 + k], sm->mw[32 + k]);
        const unsigned long long m4p = pack2(sm->mw[48 + k], sm->mw[48 + k]);

        // layer 1: 4 -> 8
        float h1[8];
#pragma unroll
        for (int o = 0; o < 8; o += 2) {
#pragma unroll
            for (int t = 0; t < 2; ++t) {
                float4 w = *(const float4*)(sm->w1 + (o + t) * 4);
                float v = P.x * w.x + P.y * w.y + ctr.x * w.z + ctr.y * w.w;
                h1[o + t] = fmaxf(fmaf(v, sm->s1[o + t], sm->b1[o + t]), 0.0f);
            }
            if (part == 0)
                facc[o / 2] = ffma2(pack2(h1[o], h1[o + 1]), m1p, facc[o / 2]);
        }
        // layer 2: 8 -> 8
        float h2[8];
#pragma unroll
        for (int o = 0; o < 8; o += 2) {
#pragma unroll
            for (int t = 0; t < 2; ++t) {
                const float4* w = (const float4*)(sm->w2 + (o + t) * 8);
                float4 wa = w[0], wb = w[1];
                float v = h1[0] * wa.x + h1[1] * wa.y + h1[2] * wa.z + h1[3] * wa.w
                        + h1[4] * wb.x + h1[5] * wb.y + h1[6] * wb.z + h1[7] * wb.w;
                h2[o + t] = fmaxf(fmaf(v, sm->s2[o + t], sm->b2[o + t]), 0.0f);
            }
            if (part == 0)
                facc[4 + o / 2] = ffma2(pack2(h2[o], h2[o + 1]), m2p, facc[4 + o / 2]);
        }
        // layer 3: 8 -> 16 (packed pairs for layer-4 dots)
        unsigned long long h3p[8];
#pragma unroll
        for (int o = 0; o < 16; o += 2) {
            float vv[2];
#pragma unroll
            for (int t = 0; t < 2; ++t) {
                const float4* w = (const float4*)(sm->w3 + (o + t) * 8);
                float4 wa = w[0], wb = w[1];
                float v = h2[0] * wa.x + h2[1] * wa.y + h2[2] * wa.z + h2[3] * wa.w
                        + h2[4] * wb.x + h2[5] * wb.y + h2[6] * wb.z + h2[7] * wb.w;
                vv[t] = fmaxf(fmaf(v, sm->s3[o + t], sm->b3[o + t]), 0.0f);
            }
            h3p[o / 2] = pack2(vv[0], vv[1]);
            if (part == 0)
                facc[8 + o / 2] = ffma2(h3p[o / 2], m3p, facc[8 + o / 2]);
        }
        // layer 4: this part's output range
#pragma unroll 1
        for (int o = obeg; o < oend; o += 2) {
            float vv[2];
#pragma unroll
            for (int t = 0; t < 2; ++t) {
                const ulonglong2* wrow = (const ulonglong2*)(sm->w4 + (o + t) * 16);
                ulonglong2 wa = wrow[0], wb = wrow[1], wc = wrow[2], wd = wrow[3];
                unsigned long long acc = ffma2(h3p[0], wa.x, 0ULL);
                acc = ffma2(h3p[1], wa.y, acc);
                acc = ffma2(h3p[2], wb.x, acc);
                acc = ffma2(h3p[3], wb.y, acc);
                acc = ffma2(h3p[4], wc.x, acc);
                acc = ffma2(h3p[5], wc.y, acc);
                acc = ffma2(h3p[6], wd.x, acc);
                acc = ffma2(h3p[7], wd.y, acc);
                float lo, hi; unpack2(acc, lo, hi);
                float v = lo + hi;
                vv[t] = fmaxf(fmaf(v, sm->s4[o + t], sm->b4[o + t]), 0.0f);
            }
            const int fi = (part ? (o - 32) : (o + 32)) >> 1;
            facc[fi] = ffma2(pack2(vv[0], vv[1]), m4p, facc[fi]);
        }
    }

    // mlp biases
    {
        const unsigned long long c3 = pack2(sm->mb[3], sm->mb[3]);
        if (part == 0) {
            const unsigned long long c0 = pack2(sm->mb[0], sm->mb[0]);
            const unsigned long long c1 = pack2(sm->mb[1], sm->mb[1]);
            const unsigned long long c2 = pack2(sm->mb[2], sm->mb[2]);
#pragma unroll
            for (int i = 0; i < 4; ++i)  facc[i]      = add2(facc[i], c0);
#pragma unroll
            for (int i = 0; i < 4; ++i)  facc[4 + i]  = add2(facc[4 + i], c1);
#pragma unroll
            for (int i = 0; i < 8; ++i)  facc[8 + i]  = add2(facc[8 + i], c2);
#pragma unroll
            for (int i = 0; i < 16; ++i) facc[16 + i] = add2(facc[16 + i], c3);
        } else {
#pragma unroll
            for (int i = 0; i < 16; ++i) facc[i] = add2(facc[i], c3);
        }
    }

    // part0 writes u64 [0..32) of g_feat row; part1 writes [32..48)
    if (part == 0) {
        ulonglong2* dst = (ulonglong2*)(g_feat + (size_t)gq * 48);
#pragma unroll
        for (int i = 0; i < 16; ++i)
            dst[i] = make_ulonglong2(facc[2 * i], facc[2 * i + 1]);
    } else {
        ulonglong2* dst = (ulonglong2*)(g_feat + (size_t)gq * 48 + 32);
#pragma unroll
        for (int i = 0; i < 8; ++i)
            dst[i] = make_ulonglong2(facc[2 * i], facc[2 * i + 1]);
    }
}

// ---------------------------------------------------------------------------
// Kernel 2b: final 96x96 GEMM + BN/ReLU + L2 normalize
// (byte-identical to rounds 6-10)
// ---------------------------------------------------------------------------
struct __align__(16) SmemGemm {
    float w5[9216];            // [96][96]
    float s5[96], b5[96];
};

extern "C" __global__ void __launch_bounds__(128)
gemm_kernel(const float* __restrict__ w5, const float* __restrict__ bn5,
            float* __restrict__ out) {
    extern __shared__ __align__(16) char smem_raw[];
    SmemGemm* sm = (SmemGemm*)smem_raw;

    const int tid = threadIdx.x;
    const int b   = blockIdx.y;

    for (int i = tid; i < 9216; i += 128) sm->w5[i] = w5[i];
    for (int i = tid; i < 96; i += 128) {
        float s = bn5[i] * rsqrtf(bn5[288 + i] + 1e-5f);
        sm->s5[i] = s; sm->b5[i] = bn5[96 + i] - bn5[192 + i] * s;
    }
    __syncthreads();

    const int half = tid & 1;
    const int n    = blockIdx.x * 64 + (tid >> 1);
    const int gq   = b * NPTS + n;

    unsigned long long fh[24];
    const ulonglong2* fsrc = (const ulonglong2*)(g_feat + (size_t)gq * 48 + half * 24);
#pragma unroll
    for (int i = 0; i < 12; ++i) {
        ulonglong2 t = fsrc[i];
        fh[2 * i] = t.x; fh[2 * i + 1] = t.y;
    }

    const int obase = half * 48;
    float* __restrict__ mybase = out + (size_t)gq * 96 + obase;
    float ss = 0.0f;

#pragma unroll 1
    for (int o = 0; o < 96; ++o) {
        const ulonglong2* wrow = (const ulonglong2*)(sm->w5 + o * 96 + half * 48);
        unsigned long long a0 = 0ULL, a1 = 0ULL;
#pragma unroll
        for (int j = 0; j < 12; ++j) {
            ulonglong2 w = wrow[j];
            a0 = ffma2(fh[2 * j],     w.x, a0);
            a1 = ffma2(fh[2 * j + 1], w.y, a1);
        }
        float lo, hi; unpack2(add2(a0, a1), lo, hi);
        float ph = lo + hi;
        float full = ph + __shfl_xor_sync(0xFFFFFFFFu, ph, 1);
        float v = fmaxf(fmaf(full, sm->s5[o], sm->b5[o]), 0.0f);
        ss = fmaf(v, v, ss);
        const int rel = o - obase;
        if ((unsigned)rel < 48u) mybase[rel] = v;   // unnormalized, own half
    }

    const float rn = rsqrtf(ss);
    float4* o4 = (float4*)mybase;
#pragma unroll 3
    for (int i = 0; i < 12; ++i) {
        float4 v = o4[i];
        v.x *= rn; v.y *= rn; v.z *= rn; v.w *= rn;
        o4[i] = v;
    }
}

// ---------------------------------------------------------------------------
// launch
// ---------------------------------------------------------------------------
extern "C" void kernel_launch(void* const* d_in, const int* in_sizes, int n_in,
                              void* d_out, int out_size) {
    const float* x   = (const float*)d_in[0];
    const float* w1  = (const float*)d_in[1];
    const float* w2  = (const float*)d_in[2];
    const float* w3  = (const float*)d_in[3];
    const float* w4  = (const float*)d_in[4];
    const float* w5  = (const float*)d_in[5];
    const float* mw  = (const float*)d_in[6];
    const float* mb  = (const float*)d_in[7];
    const float* bn1 = (const float*)d_in[8];
    const float* bn2 = (const float*)d_in[9];
    const float* bn3 = (const float*)d_in[10];
    const float* bn4 = (const float*)d_in[11];
    const float* bn5 = (const float*)d_in[12];

    const size_t knn_smem  = NPTS * 12 + 3 * 64 * 17 * 8 + 256 * QCAP * 4; // ~89.5KB
    const size_t pool_smem = sizeof(SmemPool);            // ~38.8KB
    const size_t gemm_smem = sizeof(SmemGemm);            // ~37.6KB

    cudaFuncSetAttribute(knn_kernel,  cudaFuncAttributeMaxDynamicSharedMemorySize, (int)knn_smem);
    cudaFuncSetAttribute(pool_kernel, cudaFuncAttributeMaxDynamicSharedMemorySize, (int)pool_smem);
    cudaFuncSetAttribute(gemm_kernel, cudaFuncAttributeMaxDynamicSharedMemorySize, (int)gemm_smem);

    dim3 grid(NPTS / 64, BATCH);   // 64 x 8 = 512 blocks
    knn_kernel<<<grid, 256, knn_smem>>>(x);
    pool_kernel<<<grid, 128, pool_smem>>>(x, w1, w2, w3, w4, mw, mb,
                                          bn1, bn2, bn3, bn4);
    gemm_kernel<<<grid, 128, gemm_smem>>>(w5, bn5, (float*)d_out);
}